// round 13
// baseline (speedup 1.0000x reference)
#include <cuda_runtime.h>

// LogSpaceSinkhorn: 64 independent 1024x1024 fp32 matrices.
// ls = y - u_i - v_j with y = x*log2(e)/max(tau,0.1), all base-2 log space.
// Fused row+col pass: t = 2^(y - v) staged in smem 8 rows at a time,
// u_i = lg2(S_i), column partials P_j = sum_i t_ij/S_i.
// v-update fused as a decoupled tail: the LAST CTA per matrix (atomic ticket)
// reduces all 32 P blocks and writes v' = (add? v:0) + c*lg2(sum P).
// 7 matrix reads per chunk (6 fused + finalize); chunks of 16 matrices stay
// L2-resident (64MB << 126MB).

#define NN    1024
#define BMAX  64
#define CHUNK 16
#define RB    8                    // rows per sub-tile
#define SUBS  4                    // sub-tiles per CTA -> 32 rows per CTA
#define RBLK  (NN / (RB * SUBS))   // 32 row-blocks (CTAs) per matrix

static __device__ __align__(16) float g_u[BMAX * NN];
static __device__ __align__(16) float g_v[BMAX * NN];
static __device__ __align__(16) float g_P[CHUNK * RBLK * NN];   // 2 MB partials
static __device__ int g_cnt[BMAX];                               // zero-init, self-resetting

__device__ __forceinline__ float ex2f(float x) {
    float y; asm("ex2.approx.ftz.f32 %0, %1;" : "=f"(y) : "f"(x)); return y;
}
__device__ __forceinline__ float lg2f(float x) {
    float y; asm("lg2.approx.ftz.f32 %0, %1;" : "=f"(y) : "f"(x)); return y;
}
__device__ __forceinline__ float rcpf(float x) {
    float y; asm("rcp.approx.ftz.f32 %0, %1;" : "=f"(y) : "f"(x)); return y;
}
__device__ __forceinline__ float get_scale(const float* __restrict__ tau) {
    return 1.4426950408889634f / fmaxf(*tau, 0.1f);   // log2(e)/max(tau,0.1)
}

// One matrix read -> u rows + column partials P + (last CTA) v update.
// CTA = 256 threads = 8 warps; owns 32 consecutive rows (4 sub-tiles of 8).
__global__ void __launch_bounds__(256) fused_pass(
    const float* __restrict__ a, const float* __restrict__ tau,
    int use_v, int mbase, float c, int add)
{
    __shared__ float tt[RB][NN];    // 32 KB t-tile
    __shared__ float sv[NN];        // 4 KB v
    __shared__ float sr[RB];        // 1/S per staged row
    __shared__ int   is_last;

    int cta  = blockIdx.x;                    // chunk-local: mi*RBLK + rb
    int mi   = cta >> 5;
    int rb   = cta & (RBLK - 1);
    int m    = mbase + mi;
    int tid  = threadIdx.x;
    int lane = tid & 31;
    int w    = tid >> 5;

    float scale = get_scale(tau);

    if (use_v)
        reinterpret_cast<float4*>(sv)[tid] =
            reinterpret_cast<const float4*>(g_v + (m << 10))[tid];
    else
        reinterpret_cast<float4*>(sv)[tid] = make_float4(0.f, 0.f, 0.f, 0.f);
    __syncthreads();

    float4 p = make_float4(0.f, 0.f, 0.f, 0.f);

#pragma unroll
    for (int sub = 0; sub < SUBS; ++sub) {
        // Phase A: warp per row — t = 2^(y*scale - v), stage in smem, row sum.
        int row = rb * (RB * SUBS) + sub * RB + w;
        const float* __restrict__ arow = a + ((size_t)m << 20) + ((size_t)row << 10);
        float s = 0.f;
#pragma unroll
        for (int it = 0; it < 8; ++it) {
            int j = it * 128 + lane * 4;
            float4 av = *reinterpret_cast<const float4*>(arow + j);
            float4 vv = *reinterpret_cast<const float4*>(sv + j);
            float t0 = ex2f(fmaf(av.x, scale, -vv.x));
            float t1 = ex2f(fmaf(av.y, scale, -vv.y));
            float t2 = ex2f(fmaf(av.z, scale, -vv.z));
            float t3 = ex2f(fmaf(av.w, scale, -vv.w));
            s += (t0 + t1) + (t2 + t3);
            *reinterpret_cast<float4*>(&tt[w][j]) = make_float4(t0, t1, t2, t3);
        }
#pragma unroll
        for (int o = 16; o; o >>= 1) s += __shfl_xor_sync(0xffffffffu, s, o);
        if (lane == 0) {
            g_u[(m << 10) + row] = lg2f(s);
            sr[w] = rcpf(s);
        }
        __syncthreads();

        // Phase C: thread per column quad — accumulate t/S over the 8 rows.
        float4 acc = p;
#pragma unroll
        for (int i = 0; i < RB; ++i) {
            float4 tv = *reinterpret_cast<const float4*>(&tt[i][tid * 4]);
            float ri = sr[i];
            acc.x = fmaf(tv.x, ri, acc.x);
            acc.y = fmaf(tv.y, ri, acc.y);
            acc.z = fmaf(tv.z, ri, acc.z);
            acc.w = fmaf(tv.w, ri, acc.w);
        }
        p = acc;
        __syncthreads();   // protect tt/sr before next sub-tile overwrites
    }

    *reinterpret_cast<float4*>(&g_P[((mi * RBLK + rb) << 10) + tid * 4]) = p;

    // Decoupled tail: last CTA of this matrix reduces all P blocks -> v.
    __threadfence();       // make this CTA's P writes visible before ticketing
    __syncthreads();       // all threads' stores + fences done
    if (tid == 0)
        is_last = (atomicAdd(&g_cnt[m], 1) == RBLK - 1);
    __syncthreads();
    if (is_last) {
        __threadfence();   // acquire: order P reads after the ticket
        int j = tid * 4;
        const float4* __restrict__ pp =
            reinterpret_cast<const float4*>(g_P + ((mi * RBLK) << 10) + j);
        float4 sum = make_float4(0.f, 0.f, 0.f, 0.f);
#pragma unroll
        for (int r = 0; r < RBLK; ++r) {
            float4 t = __ldcg(pp + ((size_t)r << 8));   // r*1024 floats
            sum.x += t.x; sum.y += t.y; sum.z += t.z; sum.w += t.w;
        }
        int o = (m << 10) + j;
        float4 base = add ? *reinterpret_cast<const float4*>(&g_v[o])
                          : make_float4(0.f, 0.f, 0.f, 0.f);
        float4 nv;
        nv.x = fmaf(c, lg2f(sum.x), base.x);
        nv.y = fmaf(c, lg2f(sum.y), base.y);
        nv.z = fmaf(c, lg2f(sum.z), base.z);
        nv.w = fmaf(c, lg2f(sum.w), base.w);
        *reinterpret_cast<float4*>(&g_v[o]) = nv;
        if (tid == 0) g_cnt[m] = 0;    // self-reset for next pass / graph replay
    }
}

// out_ij = 2^(y*scale - u6_i - w_j); w = 0.5*(v5+v6) already blended into g_v.
__global__ void __launch_bounds__(256) finalize_k(
    const float* __restrict__ a, const float* __restrict__ tau,
    float* __restrict__ out, int mbase)
{
    size_t e = ((size_t)(blockIdx.x * blockDim.x + threadIdx.x) << 2)
             + ((size_t)mbase << 20);
    int m   = (int)(e >> 20);
    int row = (int)(e >> 10) & 1023;
    int j   = (int)(e & 1023);

    float scale = get_scale(tau);
    float uv = g_u[(m << 10) + row];
    float4 wv = *reinterpret_cast<const float4*>(&g_v[(m << 10) + j]);
    float4 av = *reinterpret_cast<const float4*>(a + e);

    float4 r;
    r.x = ex2f(fmaf(av.x, scale, -(uv + wv.x)));
    r.y = ex2f(fmaf(av.y, scale, -(uv + wv.y)));
    r.z = ex2f(fmaf(av.z, scale, -(uv + wv.z)));
    r.w = ex2f(fmaf(av.w, scale, -(uv + wv.w)));
    *reinterpret_cast<float4*>(out + e) = r;
}

extern "C" void kernel_launch(void* const* d_in, const int* in_sizes, int n_in,
                              void* d_out, int out_size)
{
    const float* a   = (const float*)d_in[0];
    const float* tau = (const float*)d_in[1];
    float* out       = (float*)d_out;

    int b = in_sizes[0] / (NN * NN);          // 64 matrices

    for (int c0 = 0; c0 < b; c0 += CHUNK) {
        int nm = (b - c0 < CHUNK) ? (b - c0) : CHUNK;
        dim3 fg(nm * RBLK), fb(256);          // fused: 32 CTAs per matrix
        dim3 og(nm * 1024), ob(256);          // finalize

        // Iterations 1..5: u_k then v_k (v_0 = 0; first pass sets v, rest add)
        for (int it = 0; it < 5; ++it)
            fused_pass<<<fg, fb>>>(a, tau, it > 0, c0, 1.0f, it > 0);
        // Symmetric final: pass 6 gives u6 and P6 (w.r.t. v5);
        // w = v5 + 0.5*lg2(sum P6) = 0.5*(v5 + v6)
        fused_pass<<<fg, fb>>>(a, tau, 1, c0, 0.5f, 1);
        // out = 2^(y - u6 - w), chunk still L2-hot
        finalize_k<<<og, ob>>>(a, tau, out, c0);
    }
}

// round 15
// speedup vs baseline: 1.1072x; 1.1072x over previous
#include <cuda_runtime.h>

// LogSpaceSinkhorn: 64 independent 1024x1024 fp32 matrices.
// Multiplicative Sinkhorn: z = 2^(y*scale), w_j = 2^(-v_j) = rcp(sum_i z_ij/S_i)_prev,
// S_i = sum_j z_ij*w_j, u_i = lg2(S_i). Column partials P_j = sum_i z_ij/S_i are
// accumulated with float atomicAdd into a per-matrix 4KB buffer, so the next
// pass's head just does w = rcp(buf) — no reduction kernel, no P blocks.
// Triple-buffered accumulators rotate read/write/zero roles so the zero-chain
// is self-sustaining across chunks and graph replays.
// Chunks of 16 matrices stay L2-resident (64MB << 126MB).

#define NN    1024
#define BMAX  64
#define CHUNK 16
#define RB    8                    // rows per sub-tile
#define SUBS  4                    // sub-tiles per CTA -> 32 rows per CTA
#define CPM   32                   // CTAs per matrix

static __device__ __align__(16) float g_u[BMAX * NN];
static __device__ __align__(16) float g_w[BMAX * NN];          // final blend
static __device__ __align__(16) float g_B[3][CHUNK * NN];      // rotating P sums

__device__ __forceinline__ float ex2f(float x) {
    float y; asm("ex2.approx.ftz.f32 %0, %1;" : "=f"(y) : "f"(x)); return y;
}
__device__ __forceinline__ float lg2f(float x) {
    float y; asm("lg2.approx.ftz.f32 %0, %1;" : "=f"(y) : "f"(x)); return y;
}
__device__ __forceinline__ float rcpf(float x) {
    float y; asm("rcp.approx.ftz.f32 %0, %1;" : "=f"(y) : "f"(x)); return y;
}
__device__ __forceinline__ float get_scale(const float* __restrict__ tau) {
    return 1.4426950408889634f / fmaxf(*tau, 0.1f);   // log2(e)/max(tau,0.1)
}

// One pass: head w = rcp(B[br]); body = one matrix read, z staged in smem
// 8 rows at a time (cross-warp transpose), S via shfl, P via atomicAdd to B[bw].
// Also zeroes this CTA's slice of B[bz] for the NEXT pass's writer.
// CTA = 256 threads = 8 warps; owns 32 consecutive rows.
__global__ void __launch_bounds__(256) fused_pass(
    const float* __restrict__ a, const float* __restrict__ tau,
    int use_head, int save_u, int mbase, int br, int bw, int bz)
{
    __shared__ float tt[RB][NN];    // 32 KB z-tile
    __shared__ float sw[NN];        // 4 KB w
    __shared__ float sr[RB];        // 1/S per staged row

    int cta  = blockIdx.x;          // chunk-local: mi*CPM + rb
    int mi   = cta >> 5;
    int rb   = cta & (CPM - 1);
    int m    = mbase + mi;
    int tid  = threadIdx.x;
    int lane = tid & 31;
    int w    = tid >> 5;

    float scale = get_scale(tau);

    // Zero next-writer slice: grid has nm*32 CTAs; buffer used region is nm*1024
    // floats -> exactly 32 floats per CTA.
    if (tid < 32) g_B[bz][cta * 32 + tid] = 0.f;

    // Head: w_j = rcp( B[br][mi][j] ) — previous pass's completed column sums.
    if (use_head) {
        float4 s4 = reinterpret_cast<const float4*>(g_B[br] + (mi << 10))[tid];
        float4 wv;
        wv.x = rcpf(s4.x); wv.y = rcpf(s4.y); wv.z = rcpf(s4.z); wv.w = rcpf(s4.w);
        reinterpret_cast<float4*>(sw)[tid] = wv;
    } else {
        reinterpret_cast<float4*>(sw)[tid] = make_float4(1.f, 1.f, 1.f, 1.f);
    }
    __syncthreads();

    float4 p = make_float4(0.f, 0.f, 0.f, 0.f);

#pragma unroll
    for (int sub = 0; sub < SUBS; ++sub) {
        // Phase A: warp per row — z = 2^(y*scale) staged in smem,
        // S = sum_j z*w via shfl reduce.
        int row = rb * (RB * SUBS) + sub * RB + w;
        const float* __restrict__ arow = a + ((size_t)m << 20) + ((size_t)row << 10);
        float s = 0.f;
#pragma unroll
        for (int it = 0; it < 8; ++it) {
            int j = it * 128 + lane * 4;
            float4 av = *reinterpret_cast<const float4*>(arow + j);
            float4 wv = *reinterpret_cast<const float4*>(sw + j);
            float z0 = ex2f(av.x * scale);
            float z1 = ex2f(av.y * scale);
            float z2 = ex2f(av.z * scale);
            float z3 = ex2f(av.w * scale);
            s = fmaf(z0, wv.x, s); s = fmaf(z1, wv.y, s);
            s = fmaf(z2, wv.z, s); s = fmaf(z3, wv.w, s);
            *reinterpret_cast<float4*>(&tt[w][j]) = make_float4(z0, z1, z2, z3);
        }
#pragma unroll
        for (int o = 16; o; o >>= 1) s += __shfl_xor_sync(0xffffffffu, s, o);
        if (lane == 0) {
            if (save_u) g_u[(m << 10) + row] = lg2f(s);   // u6 = lg2(S) on pass 5
            sr[w] = rcpf(s);
        }
        __syncthreads();

        // Phase C: thread per column quad — p += z * (1/S) over the 8 rows.
        float4 acc = p;
#pragma unroll
        for (int i = 0; i < RB; ++i) {
            float4 zv = *reinterpret_cast<const float4*>(&tt[i][tid * 4]);
            float ri = sr[i];
            acc.x = fmaf(zv.x, ri, acc.x);
            acc.y = fmaf(zv.y, ri, acc.y);
            acc.z = fmaf(zv.z, ri, acc.z);
            acc.w = fmaf(zv.w, ri, acc.w);
        }
        p = acc;
        __syncthreads();   // protect tt/sr before next sub-tile overwrites
    }

    // Accumulate this CTA's complete 32-row column partials into B[bw].
    float* __restrict__ dst = g_B[bw] + (mi << 10) + tid * 4;
    atomicAdd(dst + 0, p.x);
    atomicAdd(dst + 1, p.y);
    atomicAdd(dst + 2, p.z);
    atomicAdd(dst + 3, p.w);
}

// Final blend: g_w = 0.5*(v5 + v6), v5 = lg2(B[1]) (sum P4), v6 = lg2(B[2]) (sum P5).
__global__ void __launch_bounds__(256) vsum_final(int mbase)
{
    int mi = blockIdx.x;
    int m  = mbase + mi;
    int t  = threadIdx.x;

    float4 s5 = reinterpret_cast<const float4*>(g_B[1] + (mi << 10))[t];
    float4 s6 = reinterpret_cast<const float4*>(g_B[2] + (mi << 10))[t];
    float4 wb;
    wb.x = 0.5f * (lg2f(s5.x) + lg2f(s6.x));
    wb.y = 0.5f * (lg2f(s5.y) + lg2f(s6.y));
    wb.z = 0.5f * (lg2f(s5.z) + lg2f(s6.z));
    wb.w = 0.5f * (lg2f(s5.w) + lg2f(s6.w));
    reinterpret_cast<float4*>(g_w + (m << 10))[t] = wb;
}

// out_ij = 2^(y*scale - u6_i - wblend_j).
__global__ void __launch_bounds__(256) finalize_k(
    const float* __restrict__ a, const float* __restrict__ tau,
    float* __restrict__ out, int mbase)
{
    size_t e = ((size_t)(blockIdx.x * blockDim.x + threadIdx.x) << 2)
             + ((size_t)mbase << 20);
    int m   = (int)(e >> 20);
    int row = (int)(e >> 10) & 1023;
    int j   = (int)(e & 1023);

    float scale = get_scale(tau);
    float uv = g_u[(m << 10) + row];
    float4 wv = *reinterpret_cast<const float4*>(&g_w[(m << 10) + j]);
    float4 av = *reinterpret_cast<const float4*>(a + e);

    float4 r;
    r.x = ex2f(fmaf(av.x, scale, -(uv + wv.x)));
    r.y = ex2f(fmaf(av.y, scale, -(uv + wv.y)));
    r.z = ex2f(fmaf(av.z, scale, -(uv + wv.z)));
    r.w = ex2f(fmaf(av.w, scale, -(uv + wv.w)));
    *reinterpret_cast<float4*>(out + e) = r;
}

extern "C" void kernel_launch(void* const* d_in, const int* in_sizes, int n_in,
                              void* d_out, int out_size)
{
    const float* a   = (const float*)d_in[0];
    const float* tau = (const float*)d_in[1];
    float* out       = (float*)d_out;

    int b = in_sizes[0] / (NN * NN);          // 64 matrices

    for (int c0 = 0; c0 < b; c0 += CHUNK) {
        int nm = (b - c0 < CHUNK) ? (b - c0) : CHUNK;
        dim3 fg(nm * CPM),  fb(256);          // 32 CTAs per matrix
        dim3 vg(nm),        vb(256);
        dim3 og(nm * 1024), ob(256);

        // 6 passes. Pass p: reads B[(p-1)%3] (w), writes B[p%3] (new P sums),
        // zeroes B[(p+1)%3] (next pass's writer). Buffer B[0] starts zero
        // (module init / previous chunk's pass 5 / previous graph replay).
        for (int p = 0; p < 6; ++p)
            fused_pass<<<fg, fb>>>(a, tau, p > 0, p == 5, c0,
                                   (p + 2) % 3, p % 3, (p + 1) % 3);
        // v5 from B[1] (sum P4), v6 from B[2] (sum P5); blend into g_w.
        vsum_final<<<vg, vb>>>(c0);
        // out = 2^(y - u6 - 0.5(v5+v6)), chunk still L2-hot.
        finalize_k<<<og, ob>>>(a, tau, out, c0);
    }
}

// round 16
// speedup vs baseline: 1.1596x; 1.0473x over previous
#include <cuda_runtime.h>

// LogSpaceSinkhorn: 64 independent 1024x1024 fp32 matrices.
// Multiplicative Sinkhorn: z = 2^(y*scale), w_j = 2^(-v_j) = rcp(sum_i z_ij/S_i)_prev,
// S_i = sum_j z_ij*w_j, u_i = lg2(S_i). Column partials P_j = sum_i z_ij/S_i are
// accumulated with vectorized float atomics into a per-matrix 4KB buffer; the
// next pass's head does w = rcp(buf). Triple-buffered accumulators rotate
// read/write/zero roles (self-sustaining across chunks and graph replays).
// Geometry: 128-thread CTAs, 16 rows each -> 1024 CTAs/chunk = ONE full wave
// at 7 CTAs/SM (launch_bounds-enforced). Chunks of 16 matrices stay L2-resident.

#define NN    1024
#define BMAX  64
#define CHUNK 16
#define RB    4                    // rows staged per sub-tile (= #warps)
#define SUBS  4                    // sub-tiles per CTA -> 16 rows per CTA
#define CPM   64                   // CTAs per matrix

static __device__ __align__(16) float g_u[BMAX * NN];
static __device__ __align__(16) float g_w[BMAX * NN];          // final blend
static __device__ __align__(16) float g_B[3][CHUNK * NN];      // rotating P sums

__device__ __forceinline__ float ex2f(float x) {
    float y; asm("ex2.approx.ftz.f32 %0, %1;" : "=f"(y) : "f"(x)); return y;
}
__device__ __forceinline__ float lg2f(float x) {
    float y; asm("lg2.approx.ftz.f32 %0, %1;" : "=f"(y) : "f"(x)); return y;
}
__device__ __forceinline__ float rcpf(float x) {
    float y; asm("rcp.approx.ftz.f32 %0, %1;" : "=f"(y) : "f"(x)); return y;
}
__device__ __forceinline__ void red_add2(float* p, float a, float b) {
    asm volatile("red.global.add.v2.f32 [%0], {%1, %2};"
                 :: "l"(p), "f"(a), "f"(b) : "memory");
}
__device__ __forceinline__ float get_scale(const float* __restrict__ tau) {
    return 1.4426950408889634f / fmaxf(*tau, 0.1f);   // log2(e)/max(tau,0.1)
}

// One pass: head w = rcp(B[br]); body = one matrix read, z staged in smem
// 4 rows at a time (cross-warp transpose), S via shfl, P via red.v2 to B[bw].
// Also zeroes this CTA's 16-float slice of B[bz] for the NEXT pass's writer.
// CTA = 128 threads = 4 warps; owns 16 consecutive rows.
__global__ void __launch_bounds__(128, 7) fused_pass(
    const float* __restrict__ a, const float* __restrict__ tau,
    int use_head, int save_u, int mbase, int br, int bw, int bz)
{
    __shared__ float tt[RB][NN];    // 16 KB z-tile
    __shared__ float sw[NN];        // 4 KB w
    __shared__ float sr[RB];        // 1/S per staged row

    int cta  = blockIdx.x;          // chunk-local: mi*CPM + rb
    int mi   = cta >> 6;
    int rb   = cta & (CPM - 1);
    int m    = mbase + mi;
    int tid  = threadIdx.x;
    int lane = tid & 31;
    int w    = tid >> 5;

    float scale = get_scale(tau);

    // Zero next-writer slice: grid = nm*64 CTAs; used region = nm*1024 floats
    // -> exactly 16 floats per CTA.
    if (tid < 16) g_B[bz][cta * 16 + tid] = 0.f;

    // Head: w_j = rcp( B[br][mi][j] ) — previous pass's completed column sums.
    if (use_head) {
#pragma unroll
        for (int k = 0; k < 2; ++k) {
            int i4 = tid + k * 128;
            float4 s4 = reinterpret_cast<const float4*>(g_B[br] + (mi << 10))[i4];
            float4 wv;
            wv.x = rcpf(s4.x); wv.y = rcpf(s4.y);
            wv.z = rcpf(s4.z); wv.w = rcpf(s4.w);
            reinterpret_cast<float4*>(sw)[i4] = wv;
        }
    } else {
#pragma unroll
        for (int k = 0; k < 2; ++k)
            reinterpret_cast<float4*>(sw)[tid + k * 128] =
                make_float4(1.f, 1.f, 1.f, 1.f);
    }
    __syncthreads();

    float4 p0 = make_float4(0.f, 0.f, 0.f, 0.f);   // cols tid*4 .. tid*4+3
    float4 p1 = make_float4(0.f, 0.f, 0.f, 0.f);   // cols 512+tid*4 ..

#pragma unroll
    for (int sub = 0; sub < SUBS; ++sub) {
        // Phase A: warp per row — z = 2^(y*scale) staged in smem,
        // S = sum_j z*w via shfl reduce.
        int row = rb * 16 + sub * RB + w;
        const float* __restrict__ arow = a + ((size_t)m << 20) + ((size_t)row << 10);
        float s = 0.f;
#pragma unroll
        for (int it = 0; it < 8; ++it) {
            int j = it * 128 + lane * 4;
            float4 av = *reinterpret_cast<const float4*>(arow + j);
            float4 wv = *reinterpret_cast<const float4*>(sw + j);
            float z0 = ex2f(av.x * scale);
            float z1 = ex2f(av.y * scale);
            float z2 = ex2f(av.z * scale);
            float z3 = ex2f(av.w * scale);
            s = fmaf(z0, wv.x, s); s = fmaf(z1, wv.y, s);
            s = fmaf(z2, wv.z, s); s = fmaf(z3, wv.w, s);
            *reinterpret_cast<float4*>(&tt[w][j]) = make_float4(z0, z1, z2, z3);
        }
#pragma unroll
        for (int o = 16; o; o >>= 1) s += __shfl_xor_sync(0xffffffffu, s, o);
        if (lane == 0) {
            if (save_u) g_u[(m << 10) + row] = lg2f(s);   // u6 on pass 5
            sr[w] = rcpf(s);
        }
        __syncthreads();

        // Phase C: thread owns two column quads — p += z * (1/S) over 4 rows.
#pragma unroll
        for (int i = 0; i < RB; ++i) {
            float ri = sr[i];
            float4 za = *reinterpret_cast<const float4*>(&tt[i][tid * 4]);
            float4 zb = *reinterpret_cast<const float4*>(&tt[i][512 + tid * 4]);
            p0.x = fmaf(za.x, ri, p0.x); p0.y = fmaf(za.y, ri, p0.y);
            p0.z = fmaf(za.z, ri, p0.z); p0.w = fmaf(za.w, ri, p0.w);
            p1.x = fmaf(zb.x, ri, p1.x); p1.y = fmaf(zb.y, ri, p1.y);
            p1.z = fmaf(zb.z, ri, p1.z); p1.w = fmaf(zb.w, ri, p1.w);
        }
        __syncthreads();   // protect tt/sr before next sub-tile overwrites
    }

    // Accumulate this CTA's complete 16-row column partials into B[bw].
    float* __restrict__ dst = g_B[bw] + (mi << 10) + tid * 4;
    red_add2(dst + 0,   p0.x, p0.y);
    red_add2(dst + 2,   p0.z, p0.w);
    red_add2(dst + 512, p1.x, p1.y);
    red_add2(dst + 514, p1.z, p1.w);
}

// Final blend: g_w = 0.5*(v5 + v6), v5 = lg2(B[1]) (sum P4), v6 = lg2(B[2]) (sum P5).
__global__ void __launch_bounds__(256) vsum_final(int mbase)
{
    int mi = blockIdx.x;
    int m  = mbase + mi;
    int t  = threadIdx.x;

    float4 s5 = reinterpret_cast<const float4*>(g_B[1] + (mi << 10))[t];
    float4 s6 = reinterpret_cast<const float4*>(g_B[2] + (mi << 10))[t];
    float4 wb;
    wb.x = 0.5f * (lg2f(s5.x) + lg2f(s6.x));
    wb.y = 0.5f * (lg2f(s5.y) + lg2f(s6.y));
    wb.z = 0.5f * (lg2f(s5.z) + lg2f(s6.z));
    wb.w = 0.5f * (lg2f(s5.w) + lg2f(s6.w));
    reinterpret_cast<float4*>(g_w + (m << 10))[t] = wb;
}

// out_ij = 2^(y*scale - u6_i - wblend_j).
__global__ void __launch_bounds__(256) finalize_k(
    const float* __restrict__ a, const float* __restrict__ tau,
    float* __restrict__ out, int mbase)
{
    size_t e = ((size_t)(blockIdx.x * blockDim.x + threadIdx.x) << 2)
             + ((size_t)mbase << 20);
    int m   = (int)(e >> 20);
    int row = (int)(e >> 10) & 1023;
    int j   = (int)(e & 1023);

    float scale = get_scale(tau);
    float uv = g_u[(m << 10) + row];
    float4 wv = *reinterpret_cast<const float4*>(&g_w[(m << 10) + j]);
    float4 av = *reinterpret_cast<const float4*>(a + e);

    float4 r;
    r.x = ex2f(fmaf(av.x, scale, -(uv + wv.x)));
    r.y = ex2f(fmaf(av.y, scale, -(uv + wv.y)));
    r.z = ex2f(fmaf(av.z, scale, -(uv + wv.z)));
    r.w = ex2f(fmaf(av.w, scale, -(uv + wv.w)));
    *reinterpret_cast<float4*>(out + e) = r;
}

extern "C" void kernel_launch(void* const* d_in, const int* in_sizes, int n_in,
                              void* d_out, int out_size)
{
    const float* a   = (const float*)d_in[0];
    const float* tau = (const float*)d_in[1];
    float* out       = (float*)d_out;

    int b = in_sizes[0] / (NN * NN);          // 64 matrices

    for (int c0 = 0; c0 < b; c0 += CHUNK) {
        int nm = (b - c0 < CHUNK) ? (b - c0) : CHUNK;
        dim3 fg(nm * CPM),  fb(128);          // 64 CTAs per matrix, one wave
        dim3 vg(nm),        vb(256);
        dim3 og(nm * 1024), ob(256);

        // 6 passes. Pass p: reads B[(p+2)%3] (w), writes B[p%3] (new P sums),
        // zeroes B[(p+1)%3] (next pass's writer). B[0] starts zero.
        for (int p = 0; p < 6; ++p)
            fused_pass<<<fg, fb>>>(a, tau, p > 0, p == 5, c0,
                                   (p + 2) % 3, p % 3, (p + 1) % 3);
        // v5 from B[1] (sum P4), v6 from B[2] (sum P5); blend into g_w.
        vsum_final<<<vg, vb>>>(c0);
        // out = 2^(y - u6 - 0.5(v5+v6)), chunk still L2-hot.
        finalize_k<<<og, ob>>>(a, tau, out, c0);
    }
}